// round 5
// baseline (speedup 1.0000x reference)
#include <cuda_runtime.h>
#include <math.h>
#include <float.h>
#include <stdint.h>

#define NN   4096
#define HID  256
#define VD   64
#define RANK0 1228

// scratch (no allocations allowed)
__device__ float  g_value[2ull * NN * HID];  // (b, j, h*64+k)  8 MB
__device__ float2 g_stats[2 * NN];           // (m_rank1228, m_rank1229)

__device__ __forceinline__ unsigned flipf(float f) {
    unsigned u = __float_as_uint(f);
    return u ^ (((unsigned)((int)u >> 31)) | 0x80000000u);
}
__device__ __forceinline__ float unflipf(unsigned k) {
    unsigned mask = (k & 0x80000000u) ? 0x80000000u : 0xFFFFFFFFu;
    return __uint_as_float(k ^ mask);
}

// ---------------------------------------------------------------------------
// value[b][j][h*64+k] = sum_c x[b][j][c] * W[h][c][k]
// grid 256 CTAs (32 j-rows each), 256 threads
// ---------------------------------------------------------------------------
__global__ void __launch_bounds__(256) k_value(const float* __restrict__ x,
                                               const float* __restrict__ wgt) {
    __shared__ float wsh[32 * 256];   // [cc][col], col = h*64+k
    __shared__ float xsh[32 * 33];
    const int t  = threadIdx.x;
    const int jt = blockIdx.x;
    const size_t base = (size_t)jt * 32 * HID;   // (b*4096 + j0)*256
    const int jj = t >> 3, cg = t & 7;

    float4 acc[8];
#pragma unroll
    for (int q = 0; q < 8; ++q) acc[q] = make_float4(0.f, 0.f, 0.f, 0.f);

    for (int ct = 0; ct < 8; ++ct) {
        __syncthreads();
#pragma unroll
        for (int s = 0; s < 32; ++s) {   // 8192 floats of weight tile
            int idx = t + 256 * s;
            int cc = idx >> 8, col = idx & 255;
            wsh[idx] = wgt[(col >> 6) * 16384 + (ct * 32 + cc) * 64 + (col & 63)];
        }
#pragma unroll
        for (int s = 0; s < 4; ++s) {    // 1024 floats of x tile
            int idx = t + 256 * s;
            int jr = idx >> 5, cc = idx & 31;
            xsh[jr * 33 + cc] = x[base + (size_t)jr * HID + ct * 32 + cc];
        }
        __syncthreads();
#pragma unroll 4
        for (int cc = 0; cc < 32; ++cc) {
            float xv = xsh[jj * 33 + cc];
#pragma unroll
            for (int qq = 0; qq < 8; ++qq) {
                int qe = (qq + cg) & 7;  // bank-conflict-free rotation
                float4 wv = *(const float4*)(wsh + cc * 256 + cg * 32 + qe * 4);
                acc[qq].x = fmaf(xv, wv.x, acc[qq].x);
                acc[qq].y = fmaf(xv, wv.y, acc[qq].y);
                acc[qq].z = fmaf(xv, wv.z, acc[qq].z);
                acc[qq].w = fmaf(xv, wv.w, acc[qq].w);
            }
        }
    }
    float* orow = g_value + base + (size_t)jj * HID + cg * 32;
#pragma unroll
    for (int qq = 0; qq < 8; ++qq) {
        int qe = (qq + cg) & 7;
        *(float4*)(orow + qe * 4) = acc[qq];
    }
}

// ---------------------------------------------------------------------------
// per (b,i) row of m: order statistics 1228 and 1229 (ascending)
// window compaction + radix select on candidates; full-window retry fallback
// grid 8192, 256 threads
// ---------------------------------------------------------------------------
__global__ void __launch_bounds__(256) k_stats(const float* __restrict__ m) {
    const int row = blockIdx.x;
    const float* p = m + (size_t)row * NN;
    __shared__ unsigned list[NN];
    __shared__ unsigned hist[256];
    __shared__ unsigned s_prefix, s_mingt;
    __shared__ int s_cnt, s_clo, s_want, s_cle;
    const int t = threadIdx.x;

    int c_lo = 0, n = 0;
    for (int attempt = 0; attempt < 2; ++attempt) {
        float lo = attempt ? -FLT_MAX : 0.26f;
        float hi = attempt ?  FLT_MAX : 0.34f;
        __syncthreads();
        if (t == 0) { s_cnt = 0; s_clo = 0; }
        __syncthreads();
        int my_lo = 0;
#pragma unroll
        for (int s = 0; s < 4; ++s) {
            float4 v = *(const float4*)(p + 4 * (t + 256 * s));
            float f[4] = {v.x, v.y, v.z, v.w};
#pragma unroll
            for (int l = 0; l < 4; ++l) {
                if (f[l] < lo) my_lo++;
                else if (attempt || f[l] < hi) {
                    int pos = atomicAdd(&s_cnt, 1);
                    list[pos] = flipf(f[l]);
                }
            }
        }
        if (my_lo) atomicAdd(&s_clo, my_lo);
        __syncthreads();
        c_lo = s_clo; n = s_cnt;
        if (c_lo <= RANK0 && c_lo + n >= RANK0 + 2) break;  // ranks covered
    }

    // radix select rank (1228 - c_lo) within list[0..n)
    unsigned prefix = 0;
    int want = RANK0 - c_lo;
    for (int shift = 24; shift >= 0; shift -= 8) {
        __syncthreads();
        hist[t] = 0;
        __syncthreads();
        unsigned sel_mask = (shift == 24) ? 0u : (0xFFFFFFFFu << (shift + 8));
        for (int i = t; i < n; i += 256) {
            unsigned k = list[i];
            if ((k & sel_mask) == prefix) atomicAdd(&hist[(k >> shift) & 255], 1u);
        }
        __syncthreads();
        if (t == 0) {
            int cum = 0;
            for (int d = 0; d < 256; ++d) {
                int c = (int)hist[d];
                if (want < cum + c) {
                    s_prefix = prefix | ((unsigned)d << shift);
                    s_want = want - cum;
                    break;
                }
                cum += c;
            }
        }
        __syncthreads();
        prefix = s_prefix; want = s_want;
    }
    unsigned key_a = prefix;   // exact rank-1228 key

    // rank 1229: count <= key_a, min of keys > key_a
    __syncthreads();
    if (t == 0) { s_cle = 0; s_mingt = 0xFFFFFFFFu; }
    __syncthreads();
    int cle = 0; unsigned mgt = 0xFFFFFFFFu;
    for (int i = t; i < n; i += 256) {
        unsigned k = list[i];
        if (k <= key_a) cle++;
        else if (k < mgt) mgt = k;
    }
    atomicAdd((unsigned*)&s_cle, (unsigned)cle);
    atomicMin(&s_mingt, mgt);
    __syncthreads();
    if (t == 0) {
        unsigned key_b = (c_lo + s_cle >= RANK0 + 2) ? key_a : s_mingt;
        g_stats[row] = make_float2(unflipf(key_a), unflipf(key_b));
    }
}

// ---------------------------------------------------------------------------
// main: out[b][i][h*64+k] = gelu( sum_j w*v / sum_j w )
// grid (64, H, B), 256 threads; CTA = 64 i-rows, one head; j-tiles of 64
// thread tile: 8i x 8k, 4-way j-split, register accumulators
// ---------------------------------------------------------------------------
__global__ void __launch_bounds__(256) k_main(const float* __restrict__ m,
                                              const float* __restrict__ r,
                                              float* __restrict__ out) {
    __shared__ float vs[64 * 64];     // v[j][k]
    __shared__ float wsm[64 * 68];    // w[j][i], stride 68 (pad)
    __shared__ float thr_s[64];
    __shared__ float dbuf[256];

    const int t  = threadIdx.x;
    const int kg = t & 7, ig = (t >> 3) & 7, js = t >> 6;
    const int h  = blockIdx.y, bz = blockIdx.z;
    const int i_base = blockIdx.x * 64;

    const float rv = r[h];
    const float r2 = __fmul_rn(rv, rv);

    if (t < 64) {
        float2 st = g_stats[bz * NN + i_base + t];
        float sa = __fmul_rn(r2, st.x);
        float sb = __fmul_rn(r2, st.y);
        thr_s[t] = __fadd_rn(__fmul_rn(0.5f, sa), __fmul_rn(0.5f, sb));
    }

    float acc[64];
#pragma unroll
    for (int q = 0; q < 64; ++q) acc[q] = 0.f;
    float den8[8];
#pragma unroll
    for (int a = 0; a < 8; ++a) den8[a] = 0.f;

    const float* mrow = m + ((size_t)bz * NN + i_base) * NN;
    const float* vsrc = g_value + (size_t)bz * NN * HID + h * VD;

    for (int jt = 0; jt < 64; ++jt) {
        const int j0 = jt * 64;
        __syncthreads();
#pragma unroll
        for (int s = 0; s < 4; ++s) {           // v tile: 1024 float4
            int f4 = t + 256 * s;
            int jj = f4 >> 4, q = (f4 & 15) * 4;
            *(float4*)(vs + jj * 64 + q) =
                *(const float4*)(vsrc + (size_t)(j0 + jj) * HID + q);
        }
#pragma unroll
        for (int s = 0; s < 16; ++s) {          // w tile: 4096 weights
            int e = t + 256 * s;
            int ii = e >> 6, jj = e & 63;
            float sv = __fmul_rn(mrow[(size_t)ii * NN + j0 + jj], r2);
            wsm[jj * 68 + ii] = (sv <= thr_s[ii]) ? __expf(-sv) : 0.f;
        }
        __syncthreads();
        const float* wrow = wsm + ig * 8;
        const float* vrow = vs + kg * 8;
#pragma unroll 4
        for (int jj = 0; jj < 16; ++jj) {
            int j = js * 16 + jj;
            float4 w0 = *(const float4*)(wrow + j * 68);
            float4 w1 = *(const float4*)(wrow + j * 68 + 4);
            float4 v0 = *(const float4*)(vrow + j * 64);
            float4 v1 = *(const float4*)(vrow + j * 64 + 4);
            float wv[8] = {w0.x, w0.y, w0.z, w0.w, w1.x, w1.y, w1.z, w1.w};
            float vv[8] = {v0.x, v0.y, v0.z, v0.w, v1.x, v1.y, v1.z, v1.w};
#pragma unroll
            for (int a = 0; a < 8; ++a)
#pragma unroll
                for (int b2 = 0; b2 < 8; ++b2)
                    acc[a * 8 + b2] = fmaf(wv[a], vv[b2], acc[a * 8 + b2]);
            if (kg == 0) {
#pragma unroll
                for (int a = 0; a < 8; ++a) den8[a] += wv[a];
            }
        }
    }

    if (kg == 0) {
#pragma unroll
        for (int a = 0; a < 8; ++a) dbuf[js * 64 + ig * 8 + a] = den8[a];
    }

    // reduce j-splits (js 1..3 -> js 0) through reused vs buffer
    float* red = vs;
    const int t64 = t & 63;
#pragma unroll
    for (int rr = 0; rr < 4; ++rr) {
        __syncthreads();
        if (js > 0) {
#pragma unroll
            for (int q = 0; q < 16; ++q)
                red[(js - 1) * 1024 + t64 * 16 + q] = acc[rr * 16 + q];
        }
        __syncthreads();
        if (js == 0) {
#pragma unroll
            for (int pp = 0; pp < 3; ++pp)
#pragma unroll
                for (int q = 0; q < 16; ++q)
                    acc[rr * 16 + q] += red[pp * 1024 + t64 * 16 + q];
        }
    }

    if (js == 0) {
#pragma unroll
        for (int a = 0; a < 8; ++a) {
            int il = ig * 8 + a;
            float den = dbuf[il] + dbuf[64 + il] + dbuf[128 + il] + dbuf[192 + il];
            float inv = 1.0f / den;
            float o[8];
#pragma unroll
            for (int b2 = 0; b2 < 8; ++b2) {
                float v = acc[a * 8 + b2] * inv;
                o[b2] = 0.5f * v * (1.0f + erff(v * 0.7071067811865475f));
            }
            float* op = out + ((size_t)bz * NN + i_base + il) * HID + h * VD + kg * 8;
            *(float4*)op       = make_float4(o[0], o[1], o[2], o[3]);
            *(float4*)(op + 4) = make_float4(o[4], o[5], o[6], o[7]);
        }
    }
}

// ---------------------------------------------------------------------------
extern "C" void kernel_launch(void* const* d_in, const int* in_sizes, int n_in,
                              void* d_out, int out_size) {
    const float *m = nullptr, *x = nullptr, *r = nullptr, *w = nullptr;
    for (int i = 0; i < n_in; ++i) {
        int s = in_sizes[i];
        if      (s == 33554432) m = (const float*)d_in[i];   // m_dist (2,4096,4096)
        else if (s == 2097152)  x = (const float*)d_in[i];   // x (2,4096,256)
        else if (s == 4)        r = (const float*)d_in[i];   // r (1,4,1,1)
        else if (s == 65536)    w = (const float*)d_in[i];   // weight (4,256,64)
    }
    float* out = (float*)d_out;

    k_value<<<256, 256>>>(x, w);
    k_stats<<<8192, 256>>>(m);
    k_main<<<dim3(64, 4, 2), 256>>>(m, r, out);
}

// round 7
// speedup vs baseline: 1.3229x; 1.3229x over previous
#include <cuda_runtime.h>
#include <math.h>
#include <float.h>
#include <stdint.h>

#define NN   4096
#define HID  256
#define VD   64
#define RANK0 1228

__device__ __align__(128) float  g_value[2ull * NN * HID];  // (b, j, h*64+k)
__device__ float2 g_stats[2 * NN];                          // (rank1228, rank1229)

__device__ __forceinline__ unsigned flipf(float f) {
    unsigned u = __float_as_uint(f);
    return u ^ (((unsigned)((int)u >> 31)) | 0x80000000u);
}
__device__ __forceinline__ float unflipf(unsigned k) {
    unsigned mask = (k & 0x80000000u) ? 0x80000000u : 0xFFFFFFFFu;
    return __uint_as_float(k ^ mask);
}
__device__ __forceinline__ void cpa16(uint32_t dst, const void* src) {
    asm volatile("cp.async.cg.shared.global [%0], [%1], 16;" :: "r"(dst), "l"(src));
}

// ---------------------------------------------------------------------------
// fused pre-kernel: blocks [0,256) -> g_value ; blocks [256,8448) -> g_stats
// Both branches are the R4 (proven) implementations verbatim.
// ---------------------------------------------------------------------------
__global__ void __launch_bounds__(256) k_pre(const float* __restrict__ x,
                                             const float* __restrict__ wgt,
                                             const float* __restrict__ m) {
    __shared__ __align__(16) float u_sm[9248];
    const int t = threadIdx.x;

    if (blockIdx.x < 256) {
        float* wsh = u_sm;              // 32 x 256
        float* xsh = u_sm + 8192;       // 32 x 33
        const size_t base = (size_t)blockIdx.x * 32 * HID;
        const int jj = t >> 3, cg = t & 7;
        float4 acc[8];
#pragma unroll
        for (int q = 0; q < 8; ++q) acc[q] = make_float4(0.f, 0.f, 0.f, 0.f);
        for (int ct = 0; ct < 8; ++ct) {
            __syncthreads();
#pragma unroll
            for (int s = 0; s < 32; ++s) {
                int idx = t + 256 * s;
                int cc = idx >> 8, col = idx & 255;
                wsh[idx] = wgt[(col >> 6) * 16384 + (ct * 32 + cc) * 64 + (col & 63)];
            }
#pragma unroll
            for (int s = 0; s < 4; ++s) {
                int idx = t + 256 * s;
                int jr = idx >> 5, cc = idx & 31;
                xsh[jr * 33 + cc] = x[base + (size_t)jr * HID + ct * 32 + cc];
            }
            __syncthreads();
#pragma unroll 4
            for (int cc = 0; cc < 32; ++cc) {
                float xv = xsh[jj * 33 + cc];
#pragma unroll
                for (int qq = 0; qq < 8; ++qq) {
                    int qe = (qq + cg) & 7;
                    float4 wv = *(const float4*)(wsh + cc * 256 + cg * 32 + qe * 4);
                    acc[qq].x = fmaf(xv, wv.x, acc[qq].x);
                    acc[qq].y = fmaf(xv, wv.y, acc[qq].y);
                    acc[qq].z = fmaf(xv, wv.z, acc[qq].z);
                    acc[qq].w = fmaf(xv, wv.w, acc[qq].w);
                }
            }
        }
        float* orow = g_value + base + (size_t)jj * HID + cg * 32;
#pragma unroll
        for (int qq = 0; qq < 8; ++qq) {
            int qe = (qq + cg) & 7;
            *(float4*)(orow + qe * 4) = acc[qq];
        }
        return;
    }

    // ---- stats branch (R4 verbatim, serial digit scan) ----
    const int row = blockIdx.x - 256;
    const float* p = m + (size_t)row * NN;
    unsigned* list = (unsigned*)u_sm;            // 4096 entries
    unsigned* hist = (unsigned*)(u_sm + 4096);   // 256 entries
    __shared__ unsigned s_prefix, s_mingt;
    __shared__ int s_cnt, s_clo, s_want, s_cle;

    int c_lo = 0, n = 0;
    for (int attempt = 0; attempt < 2; ++attempt) {
        float lo = attempt ? -FLT_MAX : 0.26f;
        float hi = attempt ?  FLT_MAX : 0.34f;
        __syncthreads();
        if (t == 0) { s_cnt = 0; s_clo = 0; }
        __syncthreads();
        int my_lo = 0;
#pragma unroll
        for (int s = 0; s < 4; ++s) {
            float4 v = *(const float4*)(p + 4 * (t + 256 * s));
            float f[4] = {v.x, v.y, v.z, v.w};
#pragma unroll
            for (int l = 0; l < 4; ++l) {
                if (f[l] < lo) my_lo++;
                else if (attempt || f[l] < hi) list[atomicAdd(&s_cnt, 1)] = flipf(f[l]);
            }
        }
        if (my_lo) atomicAdd(&s_clo, my_lo);
        __syncthreads();
        c_lo = s_clo; n = s_cnt;
        if (c_lo <= RANK0 && c_lo + n >= RANK0 + 2) break;
    }

    unsigned prefix = 0;
    int want = RANK0 - c_lo;
    for (int shift = 24; shift >= 0; shift -= 8) {
        __syncthreads();
        hist[t] = 0;
        __syncthreads();
        unsigned sel_mask = (shift == 24) ? 0u : (0xFFFFFFFFu << (shift + 8));
        for (int i = t; i < n; i += 256) {
            unsigned k = list[i];
            if ((k & sel_mask) == prefix) atomicAdd(&hist[(k >> shift) & 255], 1u);
        }
        __syncthreads();
        if (t == 0) {
            int cum = 0;
            for (int d = 0; d < 256; ++d) {
                int c = (int)hist[d];
                if (want < cum + c) {
                    s_prefix = prefix | ((unsigned)d << shift);
                    s_want = want - cum;
                    break;
                }
                cum += c;
            }
        }
        __syncthreads();
        prefix = s_prefix; want = s_want;
    }
    unsigned key_a = prefix;

    __syncthreads();
    if (t == 0) { s_cle = 0; s_mingt = 0xFFFFFFFFu; }
    __syncthreads();
    int cle = 0; unsigned mgt = 0xFFFFFFFFu;
    for (int i = t; i < n; i += 256) {
        unsigned k = list[i];
        if (k <= key_a) cle++;
        else if (k < mgt) mgt = k;
    }
    atomicAdd((unsigned*)&s_cle, (unsigned)cle);
    atomicMin(&s_mingt, mgt);
    __syncthreads();
    if (t == 0) {
        unsigned key_b = (c_lo + s_cle >= RANK0 + 2) ? key_a : s_mingt;
        g_stats[row] = make_float2(unflipf(key_a), unflipf(key_b));
    }
}

// ---------------------------------------------------------------------------
// main: R4 math paths verbatim; m/v tiles via cp.async double buffers.
// dyn smem: m[2][4096] | v[2][4096]  (64 KB). static: wsm/thr/dbuf.
// grid (64,4,2), 256 threads, 2 CTAs/SM.
// ---------------------------------------------------------------------------
__global__ void __launch_bounds__(256, 2) k_main(const float* __restrict__ m,
                                                 const float* __restrict__ r,
                                                 float* __restrict__ out) {
    extern __shared__ __align__(16) float sm[];   // [0,8192): m bufs, [8192,16384): v bufs
    __shared__ float wsm[64 * 68];    // w[j][i], stride 68 (R4 layout)
    __shared__ float thr_s[64];
    __shared__ float dbuf[256];

    const int t  = threadIdx.x;
    const int kg = t & 7, ig = (t >> 3) & 7, js = t >> 6;
    const int h  = blockIdx.y, bz = blockIdx.z;
    const int i_base = blockIdx.x * 64;

    const float rv = r[h];
    const float r2 = __fmul_rn(rv, rv);
    if (t < 64) {
        float2 st = g_stats[bz * NN + i_base + t];
        thr_s[t] = __fadd_rn(__fmul_rn(0.5f, __fmul_rn(r2, st.x)),
                             __fmul_rn(0.5f, __fmul_rn(r2, st.y)));
    }

    const float* mrow = m + ((size_t)bz * NN + i_base) * NN;
    const float* vsrc = g_value + (size_t)bz * NN * HID + h * VD;
    uint32_t sm_u = (uint32_t)__cvta_generic_to_shared(sm);

    float acc[64];
#pragma unroll
    for (int q = 0; q < 64; ++q) acc[q] = 0.f;
    float den8[8];
#pragma unroll
    for (int a = 0; a < 8; ++a) den8[a] = 0.f;

    // preload tile 0
#pragma unroll
    for (int s = 0; s < 4; ++s) {
        int q = t + 256 * s;
        cpa16(sm_u + (unsigned)q * 16, mrow + (size_t)(q >> 4) * NN + (q & 15) * 4);
    }
#pragma unroll
    for (int s = 0; s < 4; ++s) {
        int q = t + 256 * s;
        cpa16(sm_u + 32768u + (unsigned)q * 16, vsrc + (size_t)(q >> 4) * HID + (q & 15) * 4);
    }
    asm volatile("cp.async.commit_group;");

    for (int jt = 0; jt < 64; ++jt) {
        const int buf = jt & 1;
        if (jt < 63) {
            const int j0n = (jt + 1) * 64;
            const unsigned bo = (unsigned)((jt + 1) & 1);
#pragma unroll
            for (int s = 0; s < 4; ++s) {
                int q = t + 256 * s;
                cpa16(sm_u + bo * 16384u + (unsigned)q * 16,
                      mrow + (size_t)(q >> 4) * NN + j0n + (q & 15) * 4);
            }
#pragma unroll
            for (int s = 0; s < 4; ++s) {
                int q = t + 256 * s;
                cpa16(sm_u + 32768u + bo * 16384u + (unsigned)q * 16,
                      vsrc + (size_t)(j0n + (q >> 4)) * HID + (q & 15) * 4);
            }
            asm volatile("cp.async.commit_group;");
            asm volatile("cp.async.wait_group 1;");
        } else {
            asm volatile("cp.async.wait_group 0;");
        }
        __syncthreads();

        // w-stage (R4 verbatim, source = smem m tile)
        {
            const float* mb = sm + buf * 4096;
#pragma unroll
            for (int s = 0; s < 16; ++s) {
                int e = t + 256 * s;
                int ii = e >> 6, jj = e & 63;
                float sv = __fmul_rn(mb[ii * 64 + jj], r2);
                wsm[jj * 68 + ii] = (sv <= thr_s[ii]) ? __expf(-sv) : 0.f;
            }
        }
        __syncthreads();

        // compute (R4 verbatim, v from smem buffer)
        {
            const float* wrow = wsm + ig * 8;
            const float* vrow = sm + 8192 + buf * 4096 + kg * 8;
#pragma unroll 4
            for (int jj = 0; jj < 16; ++jj) {
                int j = js * 16 + jj;
                float4 w0 = *(const float4*)(wrow + j * 68);
                float4 w1 = *(const float4*)(wrow + j * 68 + 4);
                float4 v0 = *(const float4*)(vrow + j * 64);
                float4 v1 = *(const float4*)(vrow + j * 64 + 4);
                float wv[8] = {w0.x, w0.y, w0.z, w0.w, w1.x, w1.y, w1.z, w1.w};
                float vv[8] = {v0.x, v0.y, v0.z, v0.w, v1.x, v1.y, v1.z, v1.w};
#pragma unroll
                for (int a = 0; a < 8; ++a)
#pragma unroll
                    for (int b2 = 0; b2 < 8; ++b2)
                        acc[a * 8 + b2] = fmaf(wv[a], vv[b2], acc[a * 8 + b2]);
                if (kg == 0) {
#pragma unroll
                    for (int a = 0; a < 8; ++a) den8[a] += wv[a];
                }
            }
        }
        __syncthreads();
    }

    // ---- epilogue (R4 verbatim; red buffer lives in dyn smem) ----
    if (kg == 0) {
#pragma unroll
        for (int a = 0; a < 8; ++a) dbuf[js * 64 + ig * 8 + a] = den8[a];
    }

    float* red = sm;
    const int t64 = t & 63;
#pragma unroll
    for (int rr = 0; rr < 4; ++rr) {
        __syncthreads();
        if (js > 0) {
#pragma unroll
            for (int q = 0; q < 16; ++q)
                red[(js - 1) * 1024 + t64 * 16 + q] = acc[rr * 16 + q];
        }
        __syncthreads();
        if (js == 0) {
#pragma unroll
            for (int pp = 0; pp < 3; ++pp)
#pragma unroll
                for (int q = 0; q < 16; ++q)
                    acc[rr * 16 + q] += red[pp * 1024 + t64 * 16 + q];
        }
    }

    if (js == 0) {
#pragma unroll
        for (int a = 0; a < 8; ++a) {
            int il = ig * 8 + a;
            float den = dbuf[il] + dbuf[64 + il] + dbuf[128 + il] + dbuf[192 + il];
            float inv = 1.0f / den;
            float o[8];
#pragma unroll
            for (int b2 = 0; b2 < 8; ++b2) {
                float v = acc[a * 8 + b2] * inv;
                o[b2] = 0.5f * v * (1.0f + erff(v * 0.7071067811865475f));
            }
            float* op = out + ((size_t)bz * NN + i_base + il) * HID + h * VD + kg * 8;
            *(float4*)op       = make_float4(o[0], o[1], o[2], o[3]);
            *(float4*)(op + 4) = make_float4(o[4], o[5], o[6], o[7]);
        }
    }
}

// ---------------------------------------------------------------------------
extern "C" void kernel_launch(void* const* d_in, const int* in_sizes, int n_in,
                              void* d_out, int out_size) {
    const float *m = nullptr, *x = nullptr, *r = nullptr, *w = nullptr;
    for (int i = 0; i < n_in; ++i) {
        int s = in_sizes[i];
        if      (s == 33554432) m = (const float*)d_in[i];
        else if (s == 2097152)  x = (const float*)d_in[i];
        else if (s == 4)        r = (const float*)d_in[i];
        else if (s == 65536)    w = (const float*)d_in[i];
    }
    float* out = (float*)d_out;

    const int smem_main = 16384 * 4;   // 64 KB dynamic
    cudaFuncSetAttribute(k_main, cudaFuncAttributeMaxDynamicSharedMemorySize, smem_main);

    k_pre<<<256 + 8192, 256>>>(x, w, m);
    k_main<<<dim3(64, 4, 2), 256, smem_main>>>(m, r, out);
}

// round 8
// speedup vs baseline: 1.5222x; 1.1506x over previous
#include <cuda_runtime.h>
#include <math.h>
#include <float.h>
#include <stdint.h>

#define NN   4096
#define HID  256
#define VD   64
#define RANK0 1228

__device__ __align__(128) float  g_value[2ull * NN * HID];  // (b, j, h*64+k)
__device__ float2 g_stats[2 * NN];                          // (rank1228, rank1229)

__device__ __forceinline__ unsigned flipf(float f) {
    unsigned u = __float_as_uint(f);
    return u ^ (((unsigned)((int)u >> 31)) | 0x80000000u);
}
__device__ __forceinline__ float unflipf(unsigned k) {
    unsigned mask = (k & 0x80000000u) ? 0x80000000u : 0xFFFFFFFFu;
    return __uint_as_float(k ^ mask);
}
__device__ __forceinline__ void cpa16(uint32_t dst, const void* src) {
    asm volatile("cp.async.cg.shared.global [%0], [%1], 16;" :: "r"(dst), "l"(src));
}

#define PACK_F32X2(out, lo, hi) \
    asm("mov.b64 %0, {%1, %2};" : "=l"(out) : "f"(lo), "f"(hi))
#define UNPACK_F32X2(lo, hi, in) \
    asm("mov.b64 {%0, %1}, %2;" : "=f"(lo), "=f"(hi) : "l"(in))
#define FMA_F32X2(d, a, b, c) \
    asm("fma.rn.f32x2 %0, %1, %2, %3;" : "=l"(d) : "l"(a), "l"(b), "l"(c))

// ---------------------------------------------------------------------------
// fused pre-kernel: blocks [0,256) -> g_value ; blocks [256,8448) -> g_stats
// ---------------------------------------------------------------------------
__global__ void __launch_bounds__(256) k_pre(const float* __restrict__ x,
                                             const float* __restrict__ wgt,
                                             const float* __restrict__ m) {
    __shared__ __align__(16) float u_sm[9248];
    const int t = threadIdx.x;

    if (blockIdx.x < 256) {
        // ---- value branch (R6 verbatim) ----
        float* wsh = u_sm;              // 32 x 256
        float* xsh = u_sm + 8192;       // 32 x 33
        const size_t base = (size_t)blockIdx.x * 32 * HID;
        const int jj = t >> 3, cg = t & 7;
        float4 acc[8];
#pragma unroll
        for (int q = 0; q < 8; ++q) acc[q] = make_float4(0.f, 0.f, 0.f, 0.f);
        for (int ct = 0; ct < 8; ++ct) {
            __syncthreads();
#pragma unroll
            for (int s = 0; s < 32; ++s) {
                int idx = t + 256 * s;
                int cc = idx >> 8, col = idx & 255;
                wsh[idx] = wgt[(col >> 6) * 16384 + (ct * 32 + cc) * 64 + (col & 63)];
            }
#pragma unroll
            for (int s = 0; s < 4; ++s) {
                int idx = t + 256 * s;
                int jr = idx >> 5, cc = idx & 31;
                xsh[jr * 33 + cc] = x[base + (size_t)jr * HID + ct * 32 + cc];
            }
            __syncthreads();
#pragma unroll 4
            for (int cc = 0; cc < 32; ++cc) {
                float xv = xsh[jj * 33 + cc];
#pragma unroll
                for (int qq = 0; qq < 8; ++qq) {
                    int qe = (qq + cg) & 7;
                    float4 wv = *(const float4*)(wsh + cc * 256 + cg * 32 + qe * 4);
                    acc[qq].x = fmaf(xv, wv.x, acc[qq].x);
                    acc[qq].y = fmaf(xv, wv.y, acc[qq].y);
                    acc[qq].z = fmaf(xv, wv.z, acc[qq].z);
                    acc[qq].w = fmaf(xv, wv.w, acc[qq].w);
                }
            }
        }
        float* orow = g_value + base + (size_t)jj * HID + cg * 32;
#pragma unroll
        for (int qq = 0; qq < 8; ++qq) {
            int qe = (qq + cg) & 7;
            *(float4*)(orow + qe * 4) = acc[qq];
        }
        return;
    }

    // ---- stats branch: warp-aggregated compaction + parallel bin scan ----
    const int row = blockIdx.x - 256;
    const float* p = m + (size_t)row * NN;
    unsigned* list = (unsigned*)u_sm;            // 4096 entries
    unsigned* hist = (unsigned*)(u_sm + 4096);   // 256 entries
    __shared__ unsigned s_prefix, s_mingt;
    __shared__ int s_cnt, s_clo, s_want, s_cle;
    const int lane = t & 31;

    int c_lo = 0, n = 0;
    for (int attempt = 0; attempt < 2; ++attempt) {
        float lo = attempt ? -FLT_MAX : 0.26f;
        float hi = attempt ?  FLT_MAX : 0.34f;
        __syncthreads();
        if (t == 0) { s_cnt = 0; s_clo = 0; }
        __syncthreads();
        int my_lo = 0;
#pragma unroll
        for (int s = 0; s < 4; ++s) {
            float4 v = *(const float4*)(p + 4 * (t + 256 * s));
            float f[4] = {v.x, v.y, v.z, v.w};
#pragma unroll
            for (int l = 0; l < 4; ++l) {
                bool is_lo = (f[l] < lo);
                bool keep  = !is_lo && (attempt || f[l] < hi);
                if (is_lo) my_lo++;
                unsigned bal = __ballot_sync(0xffffffffu, keep);
                if (keep) {
                    int lead = __ffs(bal) - 1;
                    int pos;
                    if (lane == lead) pos = atomicAdd(&s_cnt, __popc(bal));
                    pos = __shfl_sync(bal, pos, lead);
                    pos += __popc(bal & ((1u << lane) - 1u));
                    list[pos] = flipf(f[l]);
                }
            }
        }
        if (my_lo) atomicAdd(&s_clo, my_lo);
        __syncthreads();
        c_lo = s_clo; n = s_cnt;
        if (c_lo <= RANK0 && c_lo + n >= RANK0 + 2) break;
    }

    unsigned prefix = 0;
    int want = RANK0 - c_lo;
    for (int shift = 24; shift >= 0; shift -= 8) {
        __syncthreads();
        hist[t] = 0;
        __syncthreads();
        unsigned sel_mask = (shift == 24) ? 0u : (0xFFFFFFFFu << (shift + 8));
        for (int i = t; i < n; i += 256) {
            unsigned k = list[i];
            if ((k & sel_mask) == prefix) atomicAdd(&hist[(k >> shift) & 255], 1u);
        }
        __syncthreads();
        unsigned hv = hist[t];
        // Hillis-Steele inclusive scan over 256 bins
        for (int d = 1; d < 256; d <<= 1) {
            unsigned addv = (t >= d) ? hist[t - d] : 0u;
            __syncthreads();
            hist[t] += addv;
            __syncthreads();
        }
        int incl = (int)hist[t];
        int excl = incl - (int)hv;
        if (excl <= want && want < incl) {      // exactly one t (hv>0) matches
            s_prefix = prefix | ((unsigned)t << shift);
            s_want = want - excl;
        }
        __syncthreads();
        prefix = s_prefix; want = s_want;
    }
    unsigned key_a = prefix;

    __syncthreads();
    if (t == 0) { s_cle = 0; s_mingt = 0xFFFFFFFFu; }
    __syncthreads();
    int cle = 0; unsigned mgt = 0xFFFFFFFFu;
    for (int i = t; i < n; i += 256) {
        unsigned k = list[i];
        if (k <= key_a) cle++;
        else if (k < mgt) mgt = k;
    }
    atomicAdd((unsigned*)&s_cle, (unsigned)cle);
    atomicMin(&s_mingt, mgt);
    __syncthreads();
    if (t == 0) {
        unsigned key_b = (c_lo + s_cle >= RANK0 + 2) ? key_a : s_mingt;
        g_stats[row] = make_float2(unflipf(key_a), unflipf(key_b));
    }
}

// ---------------------------------------------------------------------------
// main: R6 structure; inner product via packed fma.rn.f32x2 (FFMA2)
// dyn smem: m[2][4096] | v[2][4096]. grid (64,4,2), 256 thr, 2 CTAs/SM.
// ---------------------------------------------------------------------------
__global__ void __launch_bounds__(256, 2) k_main(const float* __restrict__ m,
                                                 const float* __restrict__ r,
                                                 float* __restrict__ out) {
    extern __shared__ __align__(16) float sm[];   // [0,8192): m bufs, [8192,16384): v bufs
    __shared__ float wsm[64 * 68];    // w[j][i], stride 68
    __shared__ float thr_s[64];
    __shared__ float dbuf[256];

    const int t  = threadIdx.x;
    const int kg = t & 7, ig = (t >> 3) & 7, js = t >> 6;
    const int h  = blockIdx.y, bz = blockIdx.z;
    const int i_base = blockIdx.x * 64;

    const float rv = r[h];
    const float r2 = __fmul_rn(rv, rv);
    if (t < 64) {
        float2 st = g_stats[bz * NN + i_base + t];
        thr_s[t] = __fadd_rn(__fmul_rn(0.5f, __fmul_rn(r2, st.x)),
                             __fmul_rn(0.5f, __fmul_rn(r2, st.y)));
    }

    const float* mrow = m + ((size_t)bz * NN + i_base) * NN;
    const float* vsrc = g_value + (size_t)bz * NN * HID + h * VD;
    uint32_t sm_u = (uint32_t)__cvta_generic_to_shared(sm);

    uint64_t acc2[32];                 // acc2[a*4+q] = (k=2q, k=2q+1) for row a
#pragma unroll
    for (int q = 0; q < 32; ++q) acc2[q] = 0ull;
    float den8[8];
#pragma unroll
    for (int a = 0; a < 8; ++a) den8[a] = 0.f;

    // preload tile 0
#pragma unroll
    for (int s = 0; s < 4; ++s) {
        int q = t + 256 * s;
        cpa16(sm_u + (unsigned)q * 16, mrow + (size_t)(q >> 4) * NN + (q & 15) * 4);
    }
#pragma unroll
    for (int s = 0; s < 4; ++s) {
        int q = t + 256 * s;
        cpa16(sm_u + 32768u + (unsigned)q * 16, vsrc + (size_t)(q >> 4) * HID + (q & 15) * 4);
    }
    asm volatile("cp.async.commit_group;");

    for (int jt = 0; jt < 64; ++jt) {
        const int buf = jt & 1;
        if (jt < 63) {
            const int j0n = (jt + 1) * 64;
            const unsigned bo = (unsigned)((jt + 1) & 1);
#pragma unroll
            for (int s = 0; s < 4; ++s) {
                int q = t + 256 * s;
                cpa16(sm_u + bo * 16384u + (unsigned)q * 16,
                      mrow + (size_t)(q >> 4) * NN + j0n + (q & 15) * 4);
            }
#pragma unroll
            for (int s = 0; s < 4; ++s) {
                int q = t + 256 * s;
                cpa16(sm_u + 32768u + bo * 16384u + (unsigned)q * 16,
                      vsrc + (size_t)(j0n + (q >> 4)) * HID + (q & 15) * 4);
            }
            asm volatile("cp.async.commit_group;");
            asm volatile("cp.async.wait_group 1;");
        } else {
            asm volatile("cp.async.wait_group 0;");
        }
        __syncthreads();

        // w-stage (R6 verbatim)
        {
            const float* mb = sm + buf * 4096;
#pragma unroll
            for (int s = 0; s < 16; ++s) {
                int e = t + 256 * s;
                int ii = e >> 6, jj = e & 63;
                float sv = __fmul_rn(mb[ii * 64 + jj], r2);
                wsm[jj * 68 + ii] = (sv <= thr_s[ii]) ? __expf(-sv) : 0.f;
            }
        }
        __syncthreads();

        // compute: packed f32x2 FMAs, same accumulation order as R6
        {
            const float* wrow = wsm + ig * 8;
            const float* vrow = sm + 8192 + buf * 4096 + kg * 8;
#pragma unroll 4
            for (int jj = 0; jj < 16; ++jj) {
                int j = js * 16 + jj;
                float4 w0 = *(const float4*)(wrow + j * 68);
                float4 w1 = *(const float4*)(wrow + j * 68 + 4);
                const float* vj = vrow + j * 64;
                uint64_t v2[4];
                v2[0] = *(const uint64_t*)(vj + 0);
                v2[1] = *(const uint64_t*)(vj + 2);
                v2[2] = *(const uint64_t*)(vj + 4);
                v2[3] = *(const uint64_t*)(vj + 6);
                float wv[8] = {w0.x, w0.y, w0.z, w0.w, w1.x, w1.y, w1.z, w1.w};
#pragma unroll
                for (int a = 0; a < 8; ++a) {
                    uint64_t wd;
                    PACK_F32X2(wd, wv[a], wv[a]);
#pragma unroll
                    for (int q = 0; q < 4; ++q)
                        FMA_F32X2(acc2[a * 4 + q], wd, v2[q], acc2[a * 4 + q]);
                }
                if (kg == 0) {
#pragma unroll
                    for (int a = 0; a < 8; ++a) den8[a] += wv[a];
                }
            }
        }
        __syncthreads();
    }

    // unpack accumulators
    float accf[64];
#pragma unroll
    for (int a = 0; a < 8; ++a)
#pragma unroll
        for (int q = 0; q < 4; ++q)
            UNPACK_F32X2(accf[a * 8 + 2 * q], accf[a * 8 + 2 * q + 1], acc2[a * 4 + q]);

    // ---- epilogue (R6 verbatim, on accf) ----
    if (kg == 0) {
#pragma unroll
        for (int a = 0; a < 8; ++a) dbuf[js * 64 + ig * 8 + a] = den8[a];
    }

    float* red = sm;
    const int t64 = t & 63;
#pragma unroll
    for (int rr = 0; rr < 4; ++rr) {
        __syncthreads();
        if (js > 0) {
#pragma unroll
            for (int q = 0; q < 16; ++q)
                red[(js - 1) * 1024 + t64 * 16 + q] = accf[rr * 16 + q];
        }
        __syncthreads();
        if (js == 0) {
#pragma unroll
            for (int pp = 0; pp < 3; ++pp)
#pragma unroll
                for (int q = 0; q < 16; ++q)
                    accf[rr * 16 + q] += red[pp * 1024 + t64 * 16 + q];
        }
    }

    if (js == 0) {
#pragma unroll
        for (int a = 0; a < 8; ++a) {
            int il = ig * 8 + a;
            float den = dbuf[il] + dbuf[64 + il] + dbuf[128 + il] + dbuf[192 + il];
            float inv = 1.0f / den;
            float o[8];
#pragma unroll
            for (int b2 = 0; b2 < 8; ++b2) {
                float v = accf[a * 8 + b2] * inv;
                o[b2] = 0.5f * v * (1.0f + erff(v * 0.7071067811865475f));
            }
            float* op = out + ((size_t)bz * NN + i_base + il) * HID + h * VD + kg * 8;
            *(float4*)op       = make_float4(o[0], o[1], o[2], o[3]);
            *(float4*)(op + 4) = make_float4(o[4], o[5], o[6], o[7]);
        }
    }
}

// ---------------------------------------------------------------------------
extern "C" void kernel_launch(void* const* d_in, const int* in_sizes, int n_in,
                              void* d_out, int out_size) {
    const float *m = nullptr, *x = nullptr, *r = nullptr, *w = nullptr;
    for (int i = 0; i < n_in; ++i) {
        int s = in_sizes[i];
        if      (s == 33554432) m = (const float*)d_in[i];
        else if (s == 2097152)  x = (const float*)d_in[i];
        else if (s == 4)        r = (const float*)d_in[i];
        else if (s == 65536)    w = (const float*)d_in[i];
    }
    float* out = (float*)d_out;

    const int smem_main = 16384 * 4;   // 64 KB dynamic
    cudaFuncSetAttribute(k_main, cudaFuncAttributeMaxDynamicSharedMemorySize, smem_main);

    k_pre<<<256 + 8192, 256>>>(x, w, m);
    k_main<<<dim3(64, 4, 2), 256, smem_main>>>(m, r, out);
}